// round 9
// baseline (speedup 1.0000x reference)
#include <cuda_runtime.h>

#define N    4096
#define K    10          // fused Jacobi steps per pass
#define BX   256         // tile width
#define BY   128         // tile height
#define HX   12          // x halo (>= K, multiple of 4 for alignment)
#define HY   10          // y halo (= K)
#define VX   232         // valid output width
#define VY   108         // valid output height
#define TXN  18          // ceil(4096/232)
#define TYN  38          // ceil(4096/108)
#define NTH  1024
#define NW   32          // warps per CTA
#define R    4           // rows per warp (NW * R == BY)

#define SCALE 0x1p-20f   // 0.25^K, exact power of two

// Scratch ping-pong buffer (allocation-free rule: __device__ global).
__device__ float g_buf[(size_t)N * N];

// dynamic smem exchange: [parity][top=0/bot=1][warp][BX floats] = 128 KB
#define EX_STRIDE  BX
#define EX_SIDE    (NW * EX_STRIDE)
#define EX_PAR     (2 * EX_SIDE)
#define SMEM_BYTES (2 * EX_PAR * (int)sizeof(float))

template<bool EDGE>
__device__ __forceinline__ void run_steps(float4 (&uL)[R], float4 (&uH)[R],
                                          float* ex, int warp, int lane,
                                          int gx0, int gy0, int ybase) {
    float4 mxL = make_float4(1.f,1.f,1.f,1.f), mxH = mxL;
    if (EDGE) {
        int g = gx0 + lane * 8;
        #pragma unroll
        for (int e = 0; e < 4; e++) {
            (&mxL.x)[e] = (g + e     >= 1 && g + e     <= N - 2) ? 1.f : 0.f;
            (&mxH.x)[e] = (g + e + 4 >= 1 && g + e + 4 <= N - 2) ? 1.f : 0.f;
        }
    }
    const int lx = lane * 8;

    #pragma unroll 2
    for (int s = 0; s < K; s++) {
        float* exP = ex + (s & 1) * EX_PAR;
        float* topP = exP + 0 * EX_SIDE + warp * EX_STRIDE + lx;
        float* botP = exP + 1 * EX_SIDE + warp * EX_STRIDE + lx;
        // publish own (old) boundary rows
        *(float4*)(topP)     = uL[0];     *(float4*)(topP + 4) = uH[0];
        *(float4*)(botP)     = uL[R-1];   *(float4*)(botP + 4) = uH[R-1];
        __syncthreads();

        float4 aL = make_float4(0,0,0,0), aH = aL;     // row above my block
        if (warp > 0) {
            const float* p = exP + 1 * EX_SIDE + (warp - 1) * EX_STRIDE + lx;
            aL = *(const float4*)p; aH = *(const float4*)(p + 4);
        }
        float4 bL = make_float4(0,0,0,0), bH = bL;     // row below my block
        if (warp < NW - 1) {
            const float* p = exP + 0 * EX_SIDE + (warp + 1) * EX_STRIDE + lx;
            bL = *(const float4*)p; bH = *(const float4*)(p + 4);
        }

        #pragma unroll
        for (int r = 0; r < R; r++) {
            float4 cL = uL[r], cH = uH[r];
            float4 dL = (r < R - 1) ? uL[r + 1] : bL;
            float4 dH = (r < R - 1) ? uH[r + 1] : bH;
            float lf = __shfl_up_sync(0xffffffffu, cH.w, 1);
            float rt = __shfl_down_sync(0xffffffffu, cL.x, 1);

            // UNSCALED sum; 0.25^K applied once in epilogue (bit-exact)
            float4 nL, nH;
            nL.x = (lf   + cL.y) + (aL.x + dL.x);
            nL.y = (cL.x + cL.z) + (aL.y + dL.y);
            nL.z = (cL.y + cL.w) + (aL.z + dL.z);
            nL.w = (cL.z + cH.x) + (aL.w + dL.w);
            nH.x = (cL.w + cH.y) + (aH.x + dH.x);
            nH.y = (cH.x + cH.z) + (aH.y + dH.y);
            nH.z = (cH.y + cH.w) + (aH.z + dH.z);
            nH.w = (cH.z + rt  ) + (aH.w + dH.w);

            if (EDGE) {
                int gy = gy0 + ybase + r;
                float my = (gy >= 1 && gy <= N - 2) ? 1.f : 0.f;
                nL.x *= my * mxL.x; nL.y *= my * mxL.y;
                nL.z *= my * mxL.z; nL.w *= my * mxL.w;
                nH.x *= my * mxH.x; nH.y *= my * mxH.y;
                nH.z *= my * mxH.z; nH.w *= my * mxH.w;
            }

            uL[r] = nL; uH[r] = nH;
            aL = cL; aH = cH;      // old values feed the next row
        }
    }
}

__device__ __forceinline__ void store_center(float4 (&uL)[R], float4 (&uH)[R],
                                             float* __restrict__ out,
                                             int warp, int lane,
                                             int gx0, int gy0, int ybase) {
    const int lx = lane * 8;
    #pragma unroll
    for (int r = 0; r < R; r++) {
        int ty = ybase + r;
        if (ty < HY || ty > BY - 1 - HY) continue;       // valid rows [10,117]
        int gy = gy0 + ty;
        if (gy >= N) continue;
        float* rowp = out + (size_t)gy * N;
        #pragma unroll
        for (int h = 0; h < 2; h++) {
            int c0 = lx + 4 * h;
            if (c0 < HX || c0 + 3 > HX + VX - 1) continue;  // valid cols [12,243]
            int gx = gx0 + c0;
            float4 v = (h == 0) ? uL[r] : uH[r];
            v.x *= SCALE; v.y *= SCALE; v.z *= SCALE; v.w *= SCALE;
            if (gx + 3 < N) {
                *(float4*)&rowp[gx] = v;
            } else {
                #pragma unroll
                for (int e = 0; e < 4; e++)
                    if (gx + e < N) rowp[gx + e] = (&v.x)[e];
            }
        }
    }
}

// ---- pass 0: compute x0 = exp(-50((X-.5)^2+(Y-.5)^2)) in-register, then K steps ----
__global__ __launch_bounds__(NTH, 1)
void jacobi_first(const float* __restrict__ X, const float* __restrict__ Y,
                  float* __restrict__ out) {
    extern __shared__ float ex[];

    const int tid   = threadIdx.x;
    const int lane  = tid & 31;
    const int warp  = tid >> 5;
    const int lx    = lane * 8;
    const int gx0   = blockIdx.x * VX - HX;
    const int gy0   = blockIdx.y * VY - HY;
    const int ybase = warp * R;

    const bool interior =
        (gx0 >= 1) && (gx0 + BX - 1 <= N - 2) &&
        (gy0 >= 1) && (gy0 + BY - 1 <= N - 2);

    float4 uL[R], uH[R];

    if (interior) {
        #pragma unroll
        for (int r = 0; r < R; r++) {
            size_t base = (size_t)(gy0 + ybase + r) * N + gx0 + lx;
            #pragma unroll
            for (int e = 0; e < 8; e++) {
                float dx = X[base + e] - 0.5f;
                float dy = Y[base + e] - 0.5f;
                float v  = __expf(-50.0f * (dx * dx + dy * dy));
                if (e < 4) (&uL[r].x)[e] = v; else (&uH[r].x)[e - 4] = v;
            }
        }
    } else {
        #pragma unroll
        for (int r = 0; r < R; r++) {
            int gy = gy0 + ybase + r;
            #pragma unroll
            for (int e = 0; e < 8; e++) {
                float v = 0.f;
                int g = gx0 + lx + e;
                if (gy >= 0 && gy < N && g >= 0 && g < N) {
                    size_t idx = (size_t)gy * N + g;
                    float dx = X[idx] - 0.5f;
                    float dy = Y[idx] - 0.5f;
                    v = __expf(-50.0f * (dx * dx + dy * dy));
                }
                if (e < 4) (&uL[r].x)[e] = v; else (&uH[r].x)[e - 4] = v;
            }
        }
    }

    if (interior) run_steps<false>(uL, uH, ex, warp, lane, gx0, gy0, ybase);
    else          run_steps<true >(uL, uH, ex, warp, lane, gx0, gy0, ybase);

    store_center(uL, uH, out, warp, lane, gx0, gy0, ybase);
}

// ---- passes 1..9: load prev state, K steps ----
__global__ __launch_bounds__(NTH, 1)
void jacobi_pass(const float* __restrict__ in, float* __restrict__ out) {
    extern __shared__ float ex[];

    const int tid   = threadIdx.x;
    const int lane  = tid & 31;
    const int warp  = tid >> 5;
    const int lx    = lane * 8;
    const int gx0   = blockIdx.x * VX - HX;
    const int gy0   = blockIdx.y * VY - HY;
    const int ybase = warp * R;

    const bool interior =
        (gx0 >= 1) && (gx0 + BX - 1 <= N - 2) &&
        (gy0 >= 1) && (gy0 + BY - 1 <= N - 2);

    float4 uL[R], uH[R];

    if (interior) {
        #pragma unroll
        for (int r = 0; r < R; r++) {
            const float* p = in + (size_t)(gy0 + ybase + r) * N + gx0 + lx;
            uL[r] = *(const float4*)p;
            uH[r] = *(const float4*)(p + 4);
        }
    } else {
        #pragma unroll
        for (int r = 0; r < R; r++) {
            int gy = gy0 + ybase + r;
            #pragma unroll
            for (int e = 0; e < 8; e++) {
                float v = 0.f;
                int g = gx0 + lx + e;
                if (gy >= 0 && gy < N && g >= 0 && g < N)
                    v = in[(size_t)gy * N + g];
                if (e < 4) (&uL[r].x)[e] = v; else (&uH[r].x)[e - 4] = v;
            }
        }
    }

    if (interior) run_steps<false>(uL, uH, ex, warp, lane, gx0, gy0, ybase);
    else          run_steps<true >(uL, uH, ex, warp, lane, gx0, gy0, ybase);

    store_center(uL, uH, out, warp, lane, gx0, gy0, ybase);
}

extern "C" void kernel_launch(void* const* d_in, const int* in_sizes, int n_in,
                              void* d_out, int out_size) {
    const float* X = (const float*)d_in[0];
    const float* Y = (const float*)d_in[1];
    float* A = (float*)d_out;
    float* B;
    cudaGetSymbolAddress((void**)&B, g_buf);

    cudaFuncSetAttribute(jacobi_first,
                         cudaFuncAttributeMaxDynamicSharedMemorySize, SMEM_BYTES);
    cudaFuncSetAttribute(jacobi_pass,
                         cudaFuncAttributeMaxDynamicSharedMemorySize, SMEM_BYTES);

    dim3 grid(TXN, TYN);

    // pass 0 (fused init + 10 steps): (X,Y) -> B
    jacobi_first<<<grid, NTH, SMEM_BYTES>>>(X, Y, B);

    // passes 1..9: odd p: B -> A, even p: A -> B; p=9 ends in A (=d_out)
    for (int p = 1; p < 10; p++) {
        const float* src = (p & 1) ? B : A;
        float*       dst = (p & 1) ? A : B;
        jacobi_pass<<<grid, NTH, SMEM_BYTES>>>(src, dst);
    }
}

// round 10
// speedup vs baseline: 1.4694x; 1.4694x over previous
#include <cuda_runtime.h>

#define N    4096
#define K    10          // fused Jacobi steps per pass
#define TX   108         // output tile edge (TX + 2K = 128)
#define BW   128         // tile edge
#define NBLK 38          // ceil(4096 / 108)
#define NTH  512
#define NW   16          // warps per CTA
#define R    8           // rows per warp (NW * R == BW)

#define SCALE 0x1p-20f   // 0.25^K, exact power of two

// Scratch ping-pong buffer (allocation-free rule: __device__ global).
__device__ float g_buf[(size_t)N * N];

// Exchange buffer type: [step parity][top=0/bot=1][warp][col]
typedef float ExBuf[2][NW][BW];

// 64-thread named barrier (two adjacent warps).
__device__ __forceinline__ void pair_bar(int id) {
    asm volatile("bar.sync %0, %1;" :: "r"(id), "r"(64) : "memory");
}

template<bool EDGE>
__device__ __forceinline__ void run_steps(float4 (&u)[R], ExBuf* ex,
                                          int warp, int x4,
                                          int gx0, int gy0, int ybase) {
    float mx0 = 1.f, mx1 = 1.f, mx2 = 1.f, mx3 = 1.f;
    if (EDGE) {
        int g = gx0 + x4;
        mx0 = (g + 0 >= 1 && g + 0 <= N - 2) ? 1.f : 0.f;
        mx1 = (g + 1 >= 1 && g + 1 <= N - 2) ? 1.f : 0.f;
        mx2 = (g + 2 >= 1 && g + 2 <= N - 2) ? 1.f : 0.f;
        mx3 = (g + 3 >= 1 && g + 3 <= N - 2) ? 1.f : 0.f;
    }

    // Nearest-neighbor sync: warp w only depends on warps w-1, w+1.
    // Even-phase pairs (0,1)(2,3)...(14,15) -> ids 1..8
    // Odd-phase  pairs (1,2)(3,4)...(13,14) -> ids 9..15
    const int eb_id = 1 + (warp >> 1);
    const int ob_id = (warp == 0 || warp == NW - 1) ? -1 : 9 + ((warp - 1) >> 1);

    #pragma unroll 2
    for (int s = 0; s < K; s++) {
        const int par = s & 1;

        // publish own boundary rows (old values) for neighbor warps
        *(float4*)&ex[par][0][warp][x4] = u[0];       // my top row
        *(float4*)&ex[par][1][warp][x4] = u[R - 1];   // my bottom row

        // sync only with the two adjacent warps (warp-uniform branches)
        pair_bar(eb_id);
        if (ob_id >= 0) pair_bar(ob_id);

        float4 above = make_float4(0.f, 0.f, 0.f, 0.f);
        if (warp > 0)
            above = *(const float4*)&ex[par][1][warp - 1][x4];
        float4 bedge = make_float4(0.f, 0.f, 0.f, 0.f);
        if (warp < NW - 1)
            bedge = *(const float4*)&ex[par][0][warp + 1][x4];

        #pragma unroll
        for (int r = 0; r < R; r++) {
            float4 cur = u[r];
            float4 dn  = (r < R - 1) ? u[r + 1] : bedge;
            float lf = __shfl_up_sync(0xffffffffu, cur.w, 1);
            float rt = __shfl_down_sync(0xffffffffu, cur.x, 1);

            // UNSCALED sum; global 0.25^K applied once in the epilogue.
            float4 nv;
            nv.x = (lf    + cur.y) + (above.x + dn.x);
            nv.y = (cur.x + cur.z) + (above.y + dn.y);
            nv.z = (cur.y + cur.w) + (above.z + dn.z);
            nv.w = (cur.z + rt   ) + (above.w + dn.w);

            if (EDGE) {
                int gy = gy0 + ybase + r;
                float my = (gy >= 1 && gy <= N - 2) ? 1.f : 0.f;
                nv.x *= my * mx0; nv.y *= my * mx1;
                nv.z *= my * mx2; nv.w *= my * mx3;
            }

            u[r]  = nv;
            above = cur;   // old value of this row feeds the next row
        }
    }
}

__device__ __forceinline__ void store_center(float4 (&u)[R], float* __restrict__ out,
                                             int warp, int lane, int x4,
                                             int gx0, int gy0, int ybase) {
    #pragma unroll
    for (int r = 0; r < R; r++) {
        int ty = ybase + r;
        if (ty < K || ty > BW - 1 - K) continue;
        int gy = gy0 + ty;
        if (gy >= N) continue;               // gy >= 0 guaranteed (ty >= K)
        float* row = out + (size_t)gy * N;
        int g = gx0 + x4;
        if (x4 + 0 >= K && x4 + 0 <= BW - 1 - K && g + 0 < N) row[g + 0] = u[r].x * SCALE;
        if (x4 + 1 >= K && x4 + 1 <= BW - 1 - K && g + 1 < N) row[g + 1] = u[r].y * SCALE;
        if (x4 + 2 >= K && x4 + 2 <= BW - 1 - K && g + 2 < N) row[g + 2] = u[r].z * SCALE;
        if (x4 + 3 >= K && x4 + 3 <= BW - 1 - K && g + 3 < N) row[g + 3] = u[r].w * SCALE;
    }
}

// ---- pass 0: compute x0 = exp(-50((X-.5)^2+(Y-.5)^2)) in-register, then K steps ----
__global__ __launch_bounds__(NTH, 2)
void jacobi_first(const float* __restrict__ X, const float* __restrict__ Y,
                  float* __restrict__ out) {
    __shared__ ExBuf ex[2];

    const int tid   = threadIdx.x;
    const int lane  = tid & 31;
    const int warp  = tid >> 5;
    const int x4    = lane * 4;
    const int gx0   = blockIdx.x * TX - K;
    const int gy0   = blockIdx.y * TX - K;
    const int ybase = warp * R;

    const bool tile_interior =
        (gx0 >= 1) && (gx0 + BW - 1 <= N - 2) &&
        (gy0 >= 1) && (gy0 + BW - 1 <= N - 2);

    float4 u[R];

    if (tile_interior) {
        #pragma unroll
        for (int r = 0; r < R; r++) {
            size_t base = (size_t)(gy0 + ybase + r) * N + gx0 + x4;
            #pragma unroll
            for (int e = 0; e < 4; e++) {
                float dx = X[base + e] - 0.5f;
                float dy = Y[base + e] - 0.5f;
                (&u[r].x)[e] = __expf(-50.0f * (dx * dx + dy * dy));
            }
        }
    } else {
        #pragma unroll
        for (int r = 0; r < R; r++) {
            int gy = gy0 + ybase + r;
            float4 v = make_float4(0.f, 0.f, 0.f, 0.f);
            if (gy >= 0 && gy < N) {
                size_t base = (size_t)gy * N;
                int g = gx0 + x4;
                #pragma unroll
                for (int e = 0; e < 4; e++) {
                    if (g + e >= 0 && g + e < N) {
                        float dx = X[base + g + e] - 0.5f;
                        float dy = Y[base + g + e] - 0.5f;
                        (&v.x)[e] = __expf(-50.0f * (dx * dx + dy * dy));
                    }
                }
            }
            u[r] = v;
        }
    }

    if (tile_interior)
        run_steps<false>(u, ex, warp, x4, gx0, gy0, ybase);
    else
        run_steps<true>(u, ex, warp, x4, gx0, gy0, ybase);

    store_center(u, out, warp, lane, x4, gx0, gy0, ybase);
}

// ---- passes 1..9: load prev state, K steps ----
__global__ __launch_bounds__(NTH, 2)
void jacobi_pass(const float* __restrict__ in, float* __restrict__ out) {
    __shared__ ExBuf ex[2];

    const int tid   = threadIdx.x;
    const int lane  = tid & 31;
    const int warp  = tid >> 5;
    const int x4    = lane * 4;
    const int gx0   = blockIdx.x * TX - K;
    const int gy0   = blockIdx.y * TX - K;
    const int ybase = warp * R;

    const bool tile_interior =
        (gx0 >= 1) && (gx0 + BW - 1 <= N - 2) &&
        (gy0 >= 1) && (gy0 + BW - 1 <= N - 2);

    float4 u[R];

    if (tile_interior) {
        #pragma unroll
        for (int r = 0; r < R; r++) {
            const float* p = in + (size_t)(gy0 + ybase + r) * N + gx0 + x4;
            u[r].x = p[0]; u[r].y = p[1]; u[r].z = p[2]; u[r].w = p[3];
        }
    } else {
        #pragma unroll
        for (int r = 0; r < R; r++) {
            int gy = gy0 + ybase + r;
            float4 v = make_float4(0.f, 0.f, 0.f, 0.f);
            if (gy >= 0 && gy < N) {
                const float* row = in + (size_t)gy * N;
                int g = gx0 + x4;
                if (g + 0 >= 0 && g + 0 < N) v.x = row[g + 0];
                if (g + 1 >= 0 && g + 1 < N) v.y = row[g + 1];
                if (g + 2 >= 0 && g + 2 < N) v.z = row[g + 2];
                if (g + 3 >= 0 && g + 3 < N) v.w = row[g + 3];
            }
            u[r] = v;
        }
    }

    if (tile_interior)
        run_steps<false>(u, ex, warp, x4, gx0, gy0, ybase);
    else
        run_steps<true>(u, ex, warp, x4, gx0, gy0, ybase);

    store_center(u, out, warp, lane, x4, gx0, gy0, ybase);
}

extern "C" void kernel_launch(void* const* d_in, const int* in_sizes, int n_in,
                              void* d_out, int out_size) {
    const float* X = (const float*)d_in[0];
    const float* Y = (const float*)d_in[1];
    float* A = (float*)d_out;
    float* B;
    cudaGetSymbolAddress((void**)&B, g_buf);

    dim3 grid(NBLK, NBLK);

    // pass 0 (fused init + 10 steps): (X,Y) -> B
    jacobi_first<<<grid, NTH>>>(X, Y, B);

    // passes 1..9: odd p: B -> A, even p: A -> B; p=9 ends in A (=d_out)
    for (int p = 1; p < 10; p++) {
        const float* src = (p & 1) ? B : A;
        float*       dst = (p & 1) ? A : B;
        jacobi_pass<<<grid, NTH>>>(src, dst);
    }
}

// round 11
// speedup vs baseline: 1.7209x; 1.1712x over previous
#include <cuda_runtime.h>

#define N    4096
#define K    10          // fused Jacobi steps per pass
#define TX   108         // output tile edge (TX + 2K = 128)
#define BW   128         // tile edge
#define NBLK 38          // ceil(4096 / 108)
#define NTH  512
#define NW   16          // warps per CTA
#define R    8           // rows per warp (NW * R == BW)

#define SCALE 0x1p-20f   // 0.25^K, exact power of two

// Scratch ping-pong buffer (allocation-free rule: __device__ global).
__device__ float g_buf[(size_t)N * N];

// Exchange buffer type: [step parity][top=0/bot=1][warp][col]
typedef float ExBuf[2][NW][BW];

template<bool EDGE>
__device__ __forceinline__ void run_steps(float4 (&u)[R], ExBuf* ex,
                                          int warp, int x4,
                                          int gx0, int gy0, int ybase) {
    float mx0 = 1.f, mx1 = 1.f, mx2 = 1.f, mx3 = 1.f;
    if (EDGE) {
        int g = gx0 + x4;
        mx0 = (g + 0 >= 1 && g + 0 <= N - 2) ? 1.f : 0.f;
        mx1 = (g + 1 >= 1 && g + 1 <= N - 2) ? 1.f : 0.f;
        mx2 = (g + 2 >= 1 && g + 2 <= N - 2) ? 1.f : 0.f;
        mx3 = (g + 3 >= 1 && g + 3 <= N - 2) ? 1.f : 0.f;
    }

    // Initial publish: step 0 reads parity-0 slots.
    *(float4*)&ex[0][0][warp][x4] = u[0];
    *(float4*)&ex[0][1][warp][x4] = u[R - 1];

    #pragma unroll 2
    for (int s = 0; s < K; s++) {
        const int par = s & 1;
        const int nxt = par ^ 1;

        // Single barrier per step. The publishes for THIS parity happened
        // deep inside the previous step's row loop -> nothing to drain here.
        __syncthreads();

        float4 above = make_float4(0.f, 0.f, 0.f, 0.f);
        if (warp > 0)
            above = *(const float4*)&ex[par][1][warp - 1][x4];
        float4 bedge = make_float4(0.f, 0.f, 0.f, 0.f);
        if (warp < NW - 1)
            bedge = *(const float4*)&ex[par][0][warp + 1][x4];

        #pragma unroll
        for (int r = 0; r < R; r++) {
            float4 cur = u[r];
            float4 dn  = (r < R - 1) ? u[r + 1] : bedge;
            float lf = __shfl_up_sync(0xffffffffu, cur.w, 1);
            float rt = __shfl_down_sync(0xffffffffu, cur.x, 1);

            // UNSCALED sum; global 0.25^K applied once in the epilogue.
            float4 nv;
            nv.x = (lf    + cur.y) + (above.x + dn.x);
            nv.y = (cur.x + cur.z) + (above.y + dn.y);
            nv.z = (cur.y + cur.w) + (above.z + dn.z);
            nv.w = (cur.z + rt   ) + (above.w + dn.w);

            if (EDGE) {
                int gy = gy0 + ybase + r;
                float my = (gy >= 1 && gy <= N - 2) ? 1.f : 0.f;
                nv.x *= my * mx0; nv.y *= my * mx1;
                nv.z *= my * mx2; nv.w *= my * mx3;
            }

            u[r] = nv;

            // Early-publish the next step's halo rows into the other parity.
            // Safe: all warps sit between the same two barriers, so parity
            // `nxt` (== s-1's parity) slots were last read before the
            // barrier above. Store drains long before the next barrier.
            if (r == 0)     *(float4*)&ex[nxt][0][warp][x4] = nv;
            if (r == R - 1) *(float4*)&ex[nxt][1][warp][x4] = nv;

            above = cur;   // old value of this row feeds the next row
        }
    }
}

__device__ __forceinline__ void store_center(float4 (&u)[R], float* __restrict__ out,
                                             int warp, int lane, int x4,
                                             int gx0, int gy0, int ybase) {
    #pragma unroll
    for (int r = 0; r < R; r++) {
        int ty = ybase + r;
        if (ty < K || ty > BW - 1 - K) continue;
        int gy = gy0 + ty;
        if (gy >= N) continue;               // gy >= 0 guaranteed (ty >= K)
        float* row = out + (size_t)gy * N;
        int g = gx0 + x4;
        if (x4 + 0 >= K && x4 + 0 <= BW - 1 - K && g + 0 < N) row[g + 0] = u[r].x * SCALE;
        if (x4 + 1 >= K && x4 + 1 <= BW - 1 - K && g + 1 < N) row[g + 1] = u[r].y * SCALE;
        if (x4 + 2 >= K && x4 + 2 <= BW - 1 - K && g + 2 < N) row[g + 2] = u[r].z * SCALE;
        if (x4 + 3 >= K && x4 + 3 <= BW - 1 - K && g + 3 < N) row[g + 3] = u[r].w * SCALE;
    }
}

// ---- pass 0: compute x0 = exp(-50((X-.5)^2+(Y-.5)^2)) in-register, then K steps ----
__global__ __launch_bounds__(NTH, 2)
void jacobi_first(const float* __restrict__ X, const float* __restrict__ Y,
                  float* __restrict__ out) {
    __shared__ ExBuf ex[2];

    const int tid   = threadIdx.x;
    const int lane  = tid & 31;
    const int warp  = tid >> 5;
    const int x4    = lane * 4;
    const int gx0   = blockIdx.x * TX - K;
    const int gy0   = blockIdx.y * TX - K;
    const int ybase = warp * R;

    const bool tile_interior =
        (gx0 >= 1) && (gx0 + BW - 1 <= N - 2) &&
        (gy0 >= 1) && (gy0 + BW - 1 <= N - 2);

    float4 u[R];

    if (tile_interior) {
        #pragma unroll
        for (int r = 0; r < R; r++) {
            size_t base = (size_t)(gy0 + ybase + r) * N + gx0 + x4;
            #pragma unroll
            for (int e = 0; e < 4; e++) {
                float dx = X[base + e] - 0.5f;
                float dy = Y[base + e] - 0.5f;
                (&u[r].x)[e] = __expf(-50.0f * (dx * dx + dy * dy));
            }
        }
    } else {
        #pragma unroll
        for (int r = 0; r < R; r++) {
            int gy = gy0 + ybase + r;
            float4 v = make_float4(0.f, 0.f, 0.f, 0.f);
            if (gy >= 0 && gy < N) {
                size_t base = (size_t)gy * N;
                int g = gx0 + x4;
                #pragma unroll
                for (int e = 0; e < 4; e++) {
                    if (g + e >= 0 && g + e < N) {
                        float dx = X[base + g + e] - 0.5f;
                        float dy = Y[base + g + e] - 0.5f;
                        (&v.x)[e] = __expf(-50.0f * (dx * dx + dy * dy));
                    }
                }
            }
            u[r] = v;
        }
    }

    if (tile_interior)
        run_steps<false>(u, ex, warp, x4, gx0, gy0, ybase);
    else
        run_steps<true>(u, ex, warp, x4, gx0, gy0, ybase);

    store_center(u, out, warp, lane, x4, gx0, gy0, ybase);
}

// ---- passes 1..9: load prev state, K steps ----
__global__ __launch_bounds__(NTH, 2)
void jacobi_pass(const float* __restrict__ in, float* __restrict__ out) {
    __shared__ ExBuf ex[2];

    const int tid   = threadIdx.x;
    const int lane  = tid & 31;
    const int warp  = tid >> 5;
    const int x4    = lane * 4;
    const int gx0   = blockIdx.x * TX - K;
    const int gy0   = blockIdx.y * TX - K;
    const int ybase = warp * R;

    const bool tile_interior =
        (gx0 >= 1) && (gx0 + BW - 1 <= N - 2) &&
        (gy0 >= 1) && (gy0 + BW - 1 <= N - 2);

    float4 u[R];

    if (tile_interior) {
        #pragma unroll
        for (int r = 0; r < R; r++) {
            const float* p = in + (size_t)(gy0 + ybase + r) * N + gx0 + x4;
            u[r].x = p[0]; u[r].y = p[1]; u[r].z = p[2]; u[r].w = p[3];
        }
    } else {
        #pragma unroll
        for (int r = 0; r < R; r++) {
            int gy = gy0 + ybase + r;
            float4 v = make_float4(0.f, 0.f, 0.f, 0.f);
            if (gy >= 0 && gy < N) {
                const float* row = in + (size_t)gy * N;
                int g = gx0 + x4;
                if (g + 0 >= 0 && g + 0 < N) v.x = row[g + 0];
                if (g + 1 >= 0 && g + 1 < N) v.y = row[g + 1];
                if (g + 2 >= 0 && g + 2 < N) v.z = row[g + 2];
                if (g + 3 >= 0 && g + 3 < N) v.w = row[g + 3];
            }
            u[r] = v;
        }
    }

    if (tile_interior)
        run_steps<false>(u, ex, warp, x4, gx0, gy0, ybase);
    else
        run_steps<true>(u, ex, warp, x4, gx0, gy0, ybase);

    store_center(u, out, warp, lane, x4, gx0, gy0, ybase);
}

extern "C" void kernel_launch(void* const* d_in, const int* in_sizes, int n_in,
                              void* d_out, int out_size) {
    const float* X = (const float*)d_in[0];
    const float* Y = (const float*)d_in[1];
    float* A = (float*)d_out;
    float* B;
    cudaGetSymbolAddress((void**)&B, g_buf);

    dim3 grid(NBLK, NBLK);

    // pass 0 (fused init + 10 steps): (X,Y) -> B
    jacobi_first<<<grid, NTH>>>(X, Y, B);

    // passes 1..9: odd p: B -> A, even p: A -> B; p=9 ends in A (=d_out)
    for (int p = 1; p < 10; p++) {
        const float* src = (p & 1) ? B : A;
        float*       dst = (p & 1) ? A : B;
        jacobi_pass<<<grid, NTH>>>(src, dst);
    }
}

// round 12
// speedup vs baseline: 1.8015x; 1.0468x over previous
#include <cuda_runtime.h>

#define N    4096
#define K    10          // fused Jacobi steps per pass
#define TX   108         // output tile edge (TX + 2K = 128)
#define BW   128         // tile edge
#define NBLK 38          // ceil(4096 / 108)
#define NTH  512
#define NW   16          // warps per CTA
#define R    8           // rows per warp (NW * R == BW)

#define SCALE 0x1p-20f   // 0.25^K, exact power of two

// Scratch ping-pong buffer (allocation-free rule: __device__ global).
__device__ float g_buf[(size_t)N * N];

// Exchange buffer type: [step parity][top=0/bot=1][warp][col]
typedef float ExBuf[2][NW][BW];

template<bool EDGE>
__device__ __forceinline__ void run_steps(float4 (&u)[R], ExBuf* ex,
                                          int warp, int x4,
                                          int gx0, int gy0, int ybase) {
    float mx0 = 1.f, mx1 = 1.f, mx2 = 1.f, mx3 = 1.f;
    if (EDGE) {
        int g = gx0 + x4;
        mx0 = (g + 0 >= 1 && g + 0 <= N - 2) ? 1.f : 0.f;
        mx1 = (g + 1 >= 1 && g + 1 <= N - 2) ? 1.f : 0.f;
        mx2 = (g + 2 >= 1 && g + 2 <= N - 2) ? 1.f : 0.f;
        mx3 = (g + 3 >= 1 && g + 3 <= N - 2) ? 1.f : 0.f;
    }

    #pragma unroll 2
    for (int s = 0; s < K; s++) {
        const int par = s & 1;

        // publish own boundary rows (old values) for neighbor warps
        *(float4*)&ex[par][0][warp][x4] = u[0];       // my top row
        *(float4*)&ex[par][1][warp][x4] = u[R - 1];   // my bottom row

        // Pre-barrier SHFLs for rows 1 and 0: operands are OLD register
        // values, independent of the exchange -> latency hides in bar wait.
        float lf1 = __shfl_up_sync(0xffffffffu, u[1].w, 1);
        float rt1 = __shfl_down_sync(0xffffffffu, u[1].x, 1);
        float lf0 = __shfl_up_sync(0xffffffffu, u[0].w, 1);
        float rt0 = __shfl_down_sync(0xffffffffu, u[0].x, 1);

        __syncthreads();

        // Issue halo LDS immediately; consumed rows later (latency hidden).
        float4 above_h = make_float4(0.f, 0.f, 0.f, 0.f);
        if (warp > 0)
            above_h = *(const float4*)&ex[par][1][warp - 1][x4];
        float4 bedge = make_float4(0.f, 0.f, 0.f, 0.f);
        if (warp < NW - 1)
            bedge = *(const float4*)&ex[par][0][warp + 1][x4];

        // ---- row 1 first: needs NO smem data ----
        float4 old0 = u[0];            // old row 0 (not yet overwritten)
        float4 cur1 = u[1];            // old row 1
        {
            float4 dn = u[2];          // old row 2
            float4 nv;
            nv.x = (lf1    + cur1.y) + (old0.x + dn.x);
            nv.y = (cur1.x + cur1.z) + (old0.y + dn.y);
            nv.z = (cur1.y + cur1.w) + (old0.z + dn.z);
            nv.w = (cur1.z + rt1   ) + (old0.w + dn.w);
            if (EDGE) {
                int gy = gy0 + ybase + 1;
                float my = (gy >= 1 && gy <= N - 2) ? 1.f : 0.f;
                nv.x *= my * mx0; nv.y *= my * mx1;
                nv.z *= my * mx2; nv.w *= my * mx3;
            }
            u[1] = nv;
        }

        // ---- row 0 second: above_h LDS has had one row of compute ----
        {
            float4 nv;
            nv.x = (lf0    + old0.y) + (above_h.x + cur1.x);
            nv.y = (old0.x + old0.z) + (above_h.y + cur1.y);
            nv.z = (old0.y + old0.w) + (above_h.z + cur1.z);
            nv.w = (old0.z + rt0   ) + (above_h.w + cur1.w);
            if (EDGE) {
                int gy = gy0 + ybase;
                float my = (gy >= 1 && gy <= N - 2) ? 1.f : 0.f;
                nv.x *= my * mx0; nv.y *= my * mx1;
                nv.z *= my * mx2; nv.w *= my * mx3;
            }
            u[0] = nv;
        }

        // ---- rows 2..7 ascending; above chain seeded with old row 1 ----
        float4 above = cur1;
        #pragma unroll
        for (int r = 2; r < R; r++) {
            float4 cur = u[r];
            float4 dn  = (r < R - 1) ? u[r + 1] : bedge;
            float lf = __shfl_up_sync(0xffffffffu, cur.w, 1);
            float rt = __shfl_down_sync(0xffffffffu, cur.x, 1);

            float4 nv;
            nv.x = (lf    + cur.y) + (above.x + dn.x);
            nv.y = (cur.x + cur.z) + (above.y + dn.y);
            nv.z = (cur.y + cur.w) + (above.z + dn.z);
            nv.w = (cur.z + rt   ) + (above.w + dn.w);

            if (EDGE) {
                int gy = gy0 + ybase + r;
                float my = (gy >= 1 && gy <= N - 2) ? 1.f : 0.f;
                nv.x *= my * mx0; nv.y *= my * mx1;
                nv.z *= my * mx2; nv.w *= my * mx3;
            }

            u[r]  = nv;
            above = cur;
        }
    }
}

__device__ __forceinline__ void store_center(float4 (&u)[R], float* __restrict__ out,
                                             int warp, int lane, int x4,
                                             int gx0, int gy0, int ybase) {
    #pragma unroll
    for (int r = 0; r < R; r++) {
        int ty = ybase + r;
        if (ty < K || ty > BW - 1 - K) continue;
        int gy = gy0 + ty;
        if (gy >= N) continue;               // gy >= 0 guaranteed (ty >= K)
        float* row = out + (size_t)gy * N;
        int g = gx0 + x4;
        if (x4 + 0 >= K && x4 + 0 <= BW - 1 - K && g + 0 < N) row[g + 0] = u[r].x * SCALE;
        if (x4 + 1 >= K && x4 + 1 <= BW - 1 - K && g + 1 < N) row[g + 1] = u[r].y * SCALE;
        if (x4 + 2 >= K && x4 + 2 <= BW - 1 - K && g + 2 < N) row[g + 2] = u[r].z * SCALE;
        if (x4 + 3 >= K && x4 + 3 <= BW - 1 - K && g + 3 < N) row[g + 3] = u[r].w * SCALE;
    }
}

// ---- pass 0: compute x0 = exp(-50((X-.5)^2+(Y-.5)^2)) in-register, then K steps ----
__global__ __launch_bounds__(NTH, 2)
void jacobi_first(const float* __restrict__ X, const float* __restrict__ Y,
                  float* __restrict__ out) {
    __shared__ ExBuf ex[2];

    const int tid   = threadIdx.x;
    const int lane  = tid & 31;
    const int warp  = tid >> 5;
    const int x4    = lane * 4;
    const int gx0   = blockIdx.x * TX - K;
    const int gy0   = blockIdx.y * TX - K;
    const int ybase = warp * R;

    const bool tile_interior =
        (gx0 >= 1) && (gx0 + BW - 1 <= N - 2) &&
        (gy0 >= 1) && (gy0 + BW - 1 <= N - 2);

    float4 u[R];

    if (tile_interior) {
        #pragma unroll
        for (int r = 0; r < R; r++) {
            size_t base = (size_t)(gy0 + ybase + r) * N + gx0 + x4;
            #pragma unroll
            for (int e = 0; e < 4; e++) {
                float dx = X[base + e] - 0.5f;
                float dy = Y[base + e] - 0.5f;
                (&u[r].x)[e] = __expf(-50.0f * (dx * dx + dy * dy));
            }
        }
    } else {
        #pragma unroll
        for (int r = 0; r < R; r++) {
            int gy = gy0 + ybase + r;
            float4 v = make_float4(0.f, 0.f, 0.f, 0.f);
            if (gy >= 0 && gy < N) {
                size_t base = (size_t)gy * N;
                int g = gx0 + x4;
                #pragma unroll
                for (int e = 0; e < 4; e++) {
                    if (g + e >= 0 && g + e < N) {
                        float dx = X[base + g + e] - 0.5f;
                        float dy = Y[base + g + e] - 0.5f;
                        (&v.x)[e] = __expf(-50.0f * (dx * dx + dy * dy));
                    }
                }
            }
            u[r] = v;
        }
    }

    if (tile_interior)
        run_steps<false>(u, ex, warp, x4, gx0, gy0, ybase);
    else
        run_steps<true>(u, ex, warp, x4, gx0, gy0, ybase);

    store_center(u, out, warp, lane, x4, gx0, gy0, ybase);
}

// ---- passes 1..9: load prev state, K steps ----
__global__ __launch_bounds__(NTH, 2)
void jacobi_pass(const float* __restrict__ in, float* __restrict__ out) {
    __shared__ ExBuf ex[2];

    const int tid   = threadIdx.x;
    const int lane  = tid & 31;
    const int warp  = tid >> 5;
    const int x4    = lane * 4;
    const int gx0   = blockIdx.x * TX - K;
    const int gy0   = blockIdx.y * TX - K;
    const int ybase = warp * R;

    const bool tile_interior =
        (gx0 >= 1) && (gx0 + BW - 1 <= N - 2) &&
        (gy0 >= 1) && (gy0 + BW - 1 <= N - 2);

    float4 u[R];

    if (tile_interior) {
        #pragma unroll
        for (int r = 0; r < R; r++) {
            const float* p = in + (size_t)(gy0 + ybase + r) * N + gx0 + x4;
            u[r].x = p[0]; u[r].y = p[1]; u[r].z = p[2]; u[r].w = p[3];
        }
    } else {
        #pragma unroll
        for (int r = 0; r < R; r++) {
            int gy = gy0 + ybase + r;
            float4 v = make_float4(0.f, 0.f, 0.f, 0.f);
            if (gy >= 0 && gy < N) {
                const float* row = in + (size_t)gy * N;
                int g = gx0 + x4;
                if (g + 0 >= 0 && g + 0 < N) v.x = row[g + 0];
                if (g + 1 >= 0 && g + 1 < N) v.y = row[g + 1];
                if (g + 2 >= 0 && g + 2 < N) v.z = row[g + 2];
                if (g + 3 >= 0 && g + 3 < N) v.w = row[g + 3];
            }
            u[r] = v;
        }
    }

    if (tile_interior)
        run_steps<false>(u, ex, warp, x4, gx0, gy0, ybase);
    else
        run_steps<true>(u, ex, warp, x4, gx0, gy0, ybase);

    store_center(u, out, warp, lane, x4, gx0, gy0, ybase);
}

extern "C" void kernel_launch(void* const* d_in, const int* in_sizes, int n_in,
                              void* d_out, int out_size) {
    const float* X = (const float*)d_in[0];
    const float* Y = (const float*)d_in[1];
    float* A = (float*)d_out;
    float* B;
    cudaGetSymbolAddress((void**)&B, g_buf);

    dim3 grid(NBLK, NBLK);

    // pass 0 (fused init + 10 steps): (X,Y) -> B
    jacobi_first<<<grid, NTH>>>(X, Y, B);

    // passes 1..9: odd p: B -> A, even p: A -> B; p=9 ends in A (=d_out)
    for (int p = 1; p < 10; p++) {
        const float* src = (p & 1) ? B : A;
        float*       dst = (p & 1) ? A : B;
        jacobi_pass<<<grid, NTH>>>(src, dst);
    }
}